// round 15
// baseline (speedup 1.0000x reference)
#include <cuda_runtime.h>
#include <cstdint>
#include <cmath>

// Problem constants
constexpr int Dm   = 1024;   // d_model
constexpr int Lb   = 1024;   // block length (SEQ / SPLIT)
constexpr int NSP  = 4;      // SPLIT
constexpr int NB   = 4;      // batch
constexpr int NH   = 16;     // heads
constexpr int DK   = 64;     // head dim
constexpr int NZ   = NB * NSP;  // 16 independent (b,s) blocks
constexpr int DW   = Dm / 2;    // 512 packed fp16-pair words per row

// Scratch (allocation-free rule: __device__ globals). All fp16, packed as
// uint32 words = 2 fp16 along the contraction/dk dim, PLAIN layout.
__device__ uint32_t g_Q[(size_t)NZ * Lb * DW];   // scaled by log2e/8 already
__device__ uint32_t g_K[(size_t)NZ * Lb * DW];
__device__ uint32_t g_V[(size_t)NZ * Lb * DW];
__device__ uint32_t g_O[(size_t)NZ * Lb * DW];
__device__ uint32_t g_Xc[(size_t)NZ * Lb * DW];
__device__ uint32_t g_Wt[(size_t)4 * NSP * Dm * DW];  // W^T [n][k-words]

__device__ __forceinline__ uint32_t pack2(float lo, float hi) {
    uint32_t r;
    asm("cvt.rn.f16x2.f32 %0, %1, %2;" : "=r"(r) : "f"(hi), "f"(lo));
    return r;
}

__device__ __forceinline__ uint32_t smem_u32(const void* p) {
    uint32_t a;
    asm("{ .reg .u64 t; cvta.to.shared.u64 t, %1; cvt.u32.u64 %0, t; }"
        : "=r"(a) : "l"(p));
    return a;
}

__device__ __forceinline__ void cp16(uint32_t dst, const void* src) {
    asm volatile("cp.async.cg.shared.global [%0], [%1], 16;"
                 :: "r"(dst), "l"(src) : "memory");
}
#define CP_COMMIT() asm volatile("cp.async.commit_group;" ::: "memory")
#define CP_WAIT1()  asm volatile("cp.async.wait_group 1;" ::: "memory")
#define CP_WAIT2()  asm volatile("cp.async.wait_group 2;" ::: "memory")

#define LDSM4(d0, d1, d2, d3, a)                                            \
    asm volatile("ldmatrix.sync.aligned.m8n8.x4.shared.b16 {%0,%1,%2,%3}, [%4];" \
        : "=r"(d0), "=r"(d1), "=r"(d2), "=r"(d3) : "r"(a))
#define LDSM4T(d0, d1, d2, d3, a)                                           \
    asm volatile("ldmatrix.sync.aligned.m8n8.x4.trans.shared.b16 {%0,%1,%2,%3}, [%4];" \
        : "=r"(d0), "=r"(d1), "=r"(d2), "=r"(d3) : "r"(a))

__device__ __forceinline__ void mma_f16(float c[4], uint32_t a0, uint32_t a1,
                                        uint32_t a2, uint32_t a3,
                                        uint32_t b0, uint32_t b1) {
    asm volatile(
        "mma.sync.aligned.m16n8k16.row.col.f32.f16.f16.f32 "
        "{%0,%1,%2,%3}, {%4,%5,%6,%7}, {%8,%9}, {%0,%1,%2,%3};\n"
        : "+f"(c[0]), "+f"(c[1]), "+f"(c[2]), "+f"(c[3])
        : "r"(a0), "r"(a1), "r"(a2), "r"(a3), "r"(b0), "r"(b1));
}

// ============================================================================
// Converts (one-time prep)
// ============================================================================
__global__ __launch_bounds__(256) void convert_x_pack(const float* __restrict__ src,
                                                      uint32_t* __restrict__ dst) {
    size_t g = (size_t)blockIdx.x * 256 + threadIdx.x;   // 8-float group
    const float4* s = (const float4*)src + g * 2;
    float4 a = s[0], b = s[1];
    uint4 o;
    o.x = pack2(a.x, a.y); o.y = pack2(a.z, a.w);
    o.z = pack2(b.x, b.y); o.w = pack2(b.z, b.w);
    ((uint4*)dst)[g] = o;
}

__global__ __launch_bounds__(256) void convert_w_t(const float* __restrict__ w0,
                                                   const float* __restrict__ w1,
                                                   const float* __restrict__ w2,
                                                   const float* __restrict__ w3,
                                                   uint32_t* __restrict__ dst) {
    __shared__ float t[32][33];
    const int zz = blockIdx.z;           // 0..15
    const int p = zz >> 2, s = zz & 3;
    const float* src = (p == 0) ? w0 : (p == 1) ? w1 : (p == 2) ? w2 : w3;
    const float* Wb = src + (size_t)s * Dm * Dm;
    uint32_t* Tw = dst + ((size_t)p * NSP + s) * Dm * DW;

    const int k0 = blockIdx.y * 32, n0 = blockIdx.x * 32;
    const int x = threadIdx.x & 31, y = threadIdx.x >> 5;   // 32 x 8
#pragma unroll
    for (int i = 0; i < 32; i += 8)
        t[y + i][x] = Wb[(size_t)(k0 + y + i) * Dm + n0 + x];
    __syncthreads();
    const int r = threadIdx.x & 31, w = threadIdx.x >> 5;   // row r, words w,w+8
    Tw[(size_t)(n0 + r) * DW + (k0 >> 1) + w]     = pack2(t[2 * w][r],      t[2 * w + 1][r]);
    Tw[(size_t)(n0 + r) * DW + (k0 >> 1) + w + 8] = pack2(t[2 * w + 16][r], t[2 * w + 17][r]);
}

// ============================================================================
// fp16 GEMM core (unchanged from round 13): 128 threads, 4 warps x 64x64,
// cp.async 3-stage, ldmatrix fragments, block(4w)-swizzle b' = b ^ ((r>>1)&3).
// ============================================================================
constexpr int GW      = 16;              // words per tile row (32 k)
constexpr int TILE_AW = 128 * GW;        // 2048 words
constexpr int STG_W   = 2 * TILE_AW;     // 4096 words = 16KB
constexpr int NSTAGE  = 3;
constexpr int GEMM_SMEM_B = NSTAGE * STG_W * 4;   // 49152 B

template <bool F16OUT>
__device__ __forceinline__ void gemm_core(const uint32_t* __restrict__ Xw,
                                          const uint32_t* __restrict__ Ww,
                                          const float* __restrict__ bz,
                                          void* __restrict__ Cz,
                                          uint32_t* smw, float sc) {
    const uint32_t sb = smem_u32(smw);
    const int m0 = blockIdx.y * 128, n0 = blockIdx.x * 128;
    const uint32_t* Xb = Xw + (size_t)m0 * DW;
    const uint32_t* Wb = Ww + (size_t)n0 * DW;
    const float* bb = bz + n0;

    const int tid = threadIdx.x;
    const int wid = tid >> 5, lane = tid & 31;
    const int gid = lane >> 2, t4 = lane & 3;
    const int wm = (wid & 1) * 64, wn = (wid >> 1) * 64;

    const int sr = tid >> 2, sb4 = tid & 3;      // staging: 32 rows/pass x 4 blocks
    auto stage = [&](int c) {
        uint32_t base = sb + (uint32_t)(c % NSTAGE) * (STG_W * 4);
#pragma unroll
        for (int i = 0; i < 4; i++) {
            int r = sr + i * 32;
            int bp = sb4 ^ ((r >> 1) & 3);
            cp16(base + (uint32_t)(r * GW + 4 * bp) * 4,
                 Xb + (size_t)r * DW + c * GW + sb4 * 4);
            cp16(base + (uint32_t)(TILE_AW + r * GW + 4 * bp) * 4,
                 Wb + (size_t)r * DW + c * GW + sb4 * 4);
        }
    };

    float acc[4][8][4];
#pragma unroll
    for (int i = 0; i < 4; i++)
#pragma unroll
        for (int j = 0; j < 8; j++)
#pragma unroll
            for (int k = 0; k < 4; k++) acc[i][j][k] = 0.f;

    stage(0); CP_COMMIT();
    stage(1); CP_COMMIT();

    const int l7 = lane & 7, l3 = (lane >> 3) & 1, l4 = lane >> 4;
    const int NCHUNK = Dm / 32;   // 32
    for (int c = 0; c < NCHUNK; c++) {
        CP_WAIT1();
        __syncthreads();
        if (c + 2 < NCHUNK) stage(c + 2);
        CP_COMMIT();

        const uint32_t sa = sb + (uint32_t)(c % NSTAGE) * (STG_W * 4);
        const uint32_t sbB = sa + TILE_AW * 4;
#pragma unroll
        for (int g = 0; g < 2; g++) {
            uint32_t af[4][4], bf[8][2];
#pragma unroll
            for (int mt = 0; mt < 4; mt++) {
                int ra = wm + mt * 16 + l7 + 8 * l3;
                int b  = 2 * g + l4;
                uint32_t ad = sa + (uint32_t)(ra * GW + 4 * (b ^ ((ra >> 1) & 3))) * 4;
                LDSM4(af[mt][0], af[mt][1], af[mt][2], af[mt][3], ad);
            }
#pragma unroll
            for (int p = 0; p < 4; p++) {
                int rb = wn + 16 * p + 8 * l4 + l7;
                int b  = 2 * g + l3;
                uint32_t ad = sbB + (uint32_t)(rb * GW + 4 * (b ^ ((rb >> 1) & 3))) * 4;
                LDSM4(bf[2 * p][0], bf[2 * p][1], bf[2 * p + 1][0], bf[2 * p + 1][1], ad);
            }
#pragma unroll
            for (int mt = 0; mt < 4; mt++)
#pragma unroll
                for (int nt = 0; nt < 8; nt++)
                    mma_f16(acc[mt][nt], af[mt][0], af[mt][1], af[mt][2], af[mt][3],
                            bf[nt][0], bf[nt][1]);
        }
    }

    // Epilogue: + bias, * sc; F16OUT packs fp16 pairs, else fp32 float2.
#pragma unroll
    for (int mt = 0; mt < 4; mt++) {
        int r0 = wm + mt * 16 + gid;
#pragma unroll
        for (int nt = 0; nt < 8; nt++) {
            int c0 = wn + nt * 8 + 2 * t4;
            float bv0 = bb[c0], bv1 = bb[c0 + 1];
            float v0 = (acc[mt][nt][0] + bv0) * sc, v1 = (acc[mt][nt][1] + bv1) * sc;
            float v2 = (acc[mt][nt][2] + bv0) * sc, v3 = (acc[mt][nt][3] + bv1) * sc;
            if (F16OUT) {
                uint32_t* Cw = (uint32_t*)Cz + (size_t)(m0) * DW + (n0 >> 1);
                int wc = (wn >> 1) + nt * 4 + t4;
                Cw[(size_t)r0 * DW + wc]       = pack2(v0, v1);
                Cw[(size_t)(r0 + 8) * DW + wc] = pack2(v2, v3);
            } else {
                float* Cf = (float*)Cz + (size_t)m0 * Dm + n0;
                *(float2*)(Cf + (size_t)r0 * Dm + c0)       = make_float2(v0, v1);
                *(float2*)(Cf + (size_t)(r0 + 8) * Dm + c0) = make_float2(v2, v3);
            }
        }
    }
}

__global__ __launch_bounds__(128) void gemm_qkv(const uint32_t* __restrict__ X,
                                                const uint32_t* __restrict__ Wt,
                                                const float* __restrict__ bq,
                                                const float* __restrict__ bk,
                                                const float* __restrict__ bv,
                                                uint32_t* __restrict__ Qo,
                                                uint32_t* __restrict__ Ko,
                                                uint32_t* __restrict__ Vo) {
    extern __shared__ uint32_t smw[];
    const int proj = blockIdx.z / NZ;
    const int z    = blockIdx.z % NZ;
    const size_t WSZ = (size_t)NSP * Dm * DW;
    const uint32_t* Xz = X + (size_t)z * Lb * DW;
    const uint32_t* Wz = Wt + proj * WSZ + (size_t)(z % NSP) * Dm * DW;
    const float* bz = ((proj == 0) ? bq : (proj == 1) ? bk : bv)
                      + (size_t)(z % NSP) * Dm;
    uint32_t* Cz = ((proj == 0) ? Qo : (proj == 1) ? Ko : Vo) + (size_t)z * Lb * DW;
    // fold 1/sqrt(DK) AND log2(e) into Q so softmax uses raw exp2
    float sc = (proj == 0) ? 0.125f * 1.44269504088896340736f : 1.0f;
    gemm_core<true>(Xz, Wz, bz, Cz, smw, sc);
}

__global__ __launch_bounds__(128) void gemm_o(const uint32_t* __restrict__ X,
                                              const uint32_t* __restrict__ Wtz4,
                                              const float* __restrict__ bo,
                                              float* __restrict__ out) {
    extern __shared__ uint32_t smw[];
    const int z = blockIdx.z;
    gemm_core<false>(X + (size_t)z * Lb * DW,
                     Wtz4 + (size_t)(z % NSP) * Dm * DW,
                     bo + (size_t)(z % NSP) * Dm,
                     out + (size_t)z * Lb * Dm, smw, 1.0f);
}

// ============================================================================
// fp16 flash attention v2: 256 threads, 128-row q-tiles. 4-stage cp.async
// K/V ring with a SINGLE barrier per key tile:
//   stage(j+2); commit; wait_group 2 (-> group j done); barrier; compute(j).
// Buffer (j+2)%4 was last read in compute(j-2); barrier(j-1) ordered that.
// exp2f softmax (log2e folded into Q projection). P stays in registers.
// ============================================================================
constexpr int KVW = 64 * 32;                       // words per K (or V) tile
constexpr int KV_STG_W = 2 * KVW;                  // K+V per stage = 4096 words
constexpr int KV_NSTG  = 4;
constexpr int Q_OFF_W  = KV_NSTG * KV_STG_W;       // 16384
constexpr int ATTN_SMEM = (Q_OFF_W + 128 * 32) * 4;  // 81920 B -> 2 CTAs/SM

__global__ __launch_bounds__(256, 2) void attn_kernel(const uint32_t* __restrict__ Q,
                                                      const uint32_t* __restrict__ K,
                                                      const uint32_t* __restrict__ V,
                                                      uint32_t* __restrict__ O) {
    extern __shared__ uint32_t sm[];
    const uint32_t sb = smem_u32(sm);
    const uint32_t qb = sb + Q_OFF_W * 4;

    const int qt = blockIdx.x;
    const int h  = blockIdx.y;
    const int z  = blockIdx.z;
    const size_t base = (size_t)z * Lb * DW + h * (DK / 2);   // word base

    const int tid = threadIdx.x;
    const int wid = tid >> 5, lane = tid & 31;
    const int gid = lane >> 2, t4 = lane & 3;
    const int wrow = wid * 16;
    const int l7 = lane & 7, l3 = (lane >> 3) & 1, l4 = lane >> 4;
    const int jlast = 2 * qt + (wid >= 4 ? 1 : 0);
    const int jend  = 2 * qt + 1;

    // Stage Q tile (already scaled by log2e/8 in projection) — with group 0
    {
        const int r8 = tid >> 3, b = tid & 7;
#pragma unroll
        for (int i = 0; i < 4; i++) {
            int r = r8 + i * 32;
            cp16(qb + (uint32_t)(r * 32 + 4 * (b ^ (r & 7))) * 4,
                 Q + base + (size_t)(qt * 128 + r) * DW + 4 * b);
        }
    }
    auto stageKV = [&](int j) {
        uint32_t kbase = sb + (uint32_t)((j & 3) * KV_STG_W) * 4;
        uint32_t vbase = kbase + (uint32_t)KVW * 4;
        const int r8 = tid >> 3, b = tid & 7;
#pragma unroll
        for (int i = 0; i < 2; i++) {
            int r = r8 + i * 32;
            uint32_t off = (uint32_t)(r * 32 + 4 * (b ^ (r & 7))) * 4;
            size_t src = base + (size_t)(j * 64 + r) * DW + 4 * b;
            cp16(kbase + off, K + src);
            cp16(vbase + off, V + src);
        }
    };

    stageKV(0); CP_COMMIT();     // group 0 also contains Q
    stageKV(1); CP_COMMIT();

    uint32_t qa[4][4];
    float acc[8][4];
#pragma unroll
    for (int nt = 0; nt < 8; nt++)
#pragma unroll
        for (int k = 0; k < 4; k++) acc[nt][k] = 0.f;
    float mrow0 = -INFINITY, mrow1 = -INFINITY;
    float lrow0 = 0.f, lrow1 = 0.f;

    for (int j = 0; j <= jend; j++) {
        if (j + 2 <= jend) stageKV(j + 2);
        CP_COMMIT();
        CP_WAIT2();          // group j complete (<=2 outstanding: j+1, j+2)
        __syncthreads();     // publish group j across warps

        if (j == 0) {   // Q landed with group 0 — load A-fragments once
#pragma unroll
            for (int g = 0; g < 4; g++) {
                int r = wrow + l7 + 8 * l3;
                int b = 2 * g + l4;
                uint32_t ad = qb + (uint32_t)(r * 32 + 4 * (b ^ (r & 7))) * 4;
                LDSM4(qa[g][0], qa[g][1], qa[g][2], qa[g][3], ad);
            }
        }

        const uint32_t kst = sb + (uint32_t)((j & 3) * KV_STG_W) * 4;
        const uint32_t vst = kst + (uint32_t)KVW * 4;

        if (j <= jlast) {
            // ---- S = Q K^T (scores pre-scaled by log2e) ----
            float s[8][4];
#pragma unroll
            for (int nt = 0; nt < 8; nt++)
#pragma unroll
                for (int k = 0; k < 4; k++) s[nt][k] = 0.f;
#pragma unroll
            for (int g = 0; g < 4; g++) {
                uint32_t kb[8][2];
#pragma unroll
                for (int p = 0; p < 4; p++) {
                    int rb = 16 * p + 8 * l4 + l7;
                    int b  = 2 * g + l3;
                    uint32_t ad = kst + (uint32_t)(rb * 32 + 4 * (b ^ (rb & 7))) * 4;
                    LDSM4(kb[2 * p][0], kb[2 * p][1], kb[2 * p + 1][0], kb[2 * p + 1][1], ad);
                }
#pragma unroll
                for (int nt = 0; nt < 8; nt++)
                    mma_f16(s[nt], qa[g][0], qa[g][1], qa[g][2], qa[g][3],
                            kb[nt][0], kb[nt][1]);
            }

            // ---- causal mask on the warp's final tile ----
            if (j == jlast) {
                int koff = (j - 2 * qt) * 64;
                int r0 = wrow + gid, r1 = wrow + gid + 8;
#pragma unroll
                for (int nt = 0; nt < 8; nt++) {
                    int c0 = koff + nt * 8 + 2 * t4;
                    if (c0 > r0)     s[nt][0] = -1e30f;
                    if (c0 + 1 > r0) s[nt][1] = -1e30f;
                    if (c0 > r1)     s[nt][2] = -1e30f;
                    if (c0 + 1 > r1) s[nt][3] = -1e30f;
                }
            }

            // ---- online softmax (fp32, base-2) ----
            float mx0 = -INFINITY, mx1 = -INFINITY;
#pragma unroll
            for (int nt = 0; nt < 8; nt++) {
                mx0 = fmaxf(mx0, fmaxf(s[nt][0], s[nt][1]));
                mx1 = fmaxf(mx1, fmaxf(s[nt][2], s[nt][3]));
            }
            mx0 = fmaxf(mx0, __shfl_xor_sync(0xffffffffu, mx0, 1));
            mx0 = fmaxf(mx0, __shfl_xor_sync(0xffffffffu, mx0, 2));
            mx1 = fmaxf(mx1, __shfl_xor_sync(0xffffffffu, mx1, 1));
            mx1 = fmaxf(mx1, __shfl_xor_sync(0xffffffffu, mx1, 2));

            float mn0 = fmaxf(mrow0, mx0), mn1 = fmaxf(mrow1, mx1);
            float cor0 = exp2f(mrow0 - mn0), cor1 = exp2f(mrow1 - mn1);
            mrow0 = mn0; mrow1 = mn1;

            float ls0 = 0.f, ls1 = 0.f;
#pragma unroll
            for (int nt = 0; nt < 8; nt++) {
                s[nt][0] = exp2f(s[nt][0] - mn0);
                s[nt][1] = exp2f(s[nt][1] - mn0);
                s[nt][2] = exp2f(s[nt][2] - mn1);
                s[nt][3] = exp2f(s[nt][3] - mn1);
                ls0 += s[nt][0] + s[nt][1];
                ls1 += s[nt][2] + s[nt][3];
            }
            ls0 += __shfl_xor_sync(0xffffffffu, ls0, 1);
            ls0 += __shfl_xor_sync(0xffffffffu, ls0, 2);
            ls1 += __shfl_xor_sync(0xffffffffu, ls1, 1);
            ls1 += __shfl_xor_sync(0xffffffffu, ls1, 2);
            lrow0 = lrow0 * cor0 + ls0;
            lrow1 = lrow1 * cor1 + ls1;

#pragma unroll
            for (int nt = 0; nt < 8; nt++) {
                acc[nt][0] *= cor0; acc[nt][1] *= cor0;
                acc[nt][2] *= cor1; acc[nt][3] *= cor1;
            }

            // ---- O += P V : P packed straight from registers ----
#pragma unroll
            for (int g = 0; g < 4; g++) {
                uint32_t pa0 = pack2(s[2 * g][0],     s[2 * g][1]);
                uint32_t pa1 = pack2(s[2 * g][2],     s[2 * g][3]);
                uint32_t pa2 = pack2(s[2 * g + 1][0], s[2 * g + 1][1]);
                uint32_t pa3 = pack2(s[2 * g + 1][2], s[2 * g + 1][3]);
                uint32_t vb[8][2];
#pragma unroll
                for (int p = 0; p < 4; p++) {
                    int rv = 16 * g + l7 + 8 * l3;
                    int b  = 2 * p + l4;
                    uint32_t ad = vst + (uint32_t)(rv * 32 + 4 * (b ^ (rv & 7))) * 4;
                    LDSM4T(vb[2 * p][0], vb[2 * p][1], vb[2 * p + 1][0], vb[2 * p + 1][1], ad);
                }
#pragma unroll
                for (int nt = 0; nt < 8; nt++)
                    mma_f16(acc[nt], pa0, pa1, pa2, pa3, vb[nt][0], vb[nt][1]);
            }
        }
    }

    // Finalize: /rowsum, pack fp16, plain layout
    float inv0 = 1.f / lrow0, inv1 = 1.f / lrow1;
    int r0 = qt * 128 + wrow + gid;
#pragma unroll
    for (int nt = 0; nt < 8; nt++) {
        int wc = nt * 4 + t4;
        O[base + (size_t)r0 * DW + wc]       = pack2(acc[nt][0] * inv0, acc[nt][1] * inv0);
        O[base + (size_t)(r0 + 8) * DW + wc] = pack2(acc[nt][2] * inv1, acc[nt][3] * inv1);
    }
}

// ============================================================================
// Launch
// ============================================================================
extern "C" void kernel_launch(void* const* d_in, const int* in_sizes, int n_in,
                              void* d_out, int out_size) {
    const float* x  = (const float*)d_in[0];
    const float* Wq = (const float*)d_in[1];
    const float* Wk = (const float*)d_in[2];
    const float* Wv = (const float*)d_in[3];
    const float* Wo = (const float*)d_in[4];
    const float* bq = (const float*)d_in[5];
    const float* bk = (const float*)d_in[6];
    const float* bv = (const float*)d_in[7];
    const float* bo = (const float*)d_in[8];
    float* out = (float*)d_out;

    uint32_t *gq, *gk, *gv, *go, *gxc, *gwt;
    cudaGetSymbolAddress((void**)&gq, g_Q);
    cudaGetSymbolAddress((void**)&gk, g_K);
    cudaGetSymbolAddress((void**)&gv, g_V);
    cudaGetSymbolAddress((void**)&go, g_O);
    cudaGetSymbolAddress((void**)&gxc, g_Xc);
    cudaGetSymbolAddress((void**)&gwt, g_Wt);
    const size_t WSZ = (size_t)NSP * Dm * DW;

    cudaFuncSetAttribute(attn_kernel, cudaFuncAttributeMaxDynamicSharedMemorySize,
                         ATTN_SMEM);
    cudaFuncSetAttribute(gemm_qkv, cudaFuncAttributeMaxDynamicSharedMemorySize,
                         GEMM_SMEM_B);
    cudaFuncSetAttribute(gemm_o, cudaFuncAttributeMaxDynamicSharedMemorySize,
                         GEMM_SMEM_B);

    const size_t XG = (size_t)NZ * Lb * Dm / 8;     // 8-float groups
    convert_x_pack<<<(unsigned)(XG / 256), 256>>>(x, gxc);
    convert_w_t<<<dim3(32, 32, 16), 256>>>(Wq, Wk, Wv, Wo, gwt);

    gemm_qkv<<<dim3(Dm / 128, Lb / 128, NZ * 3), 128, GEMM_SMEM_B>>>(
        gxc, gwt, bq, bk, bv, gq, gk, gv);

    attn_kernel<<<dim3(Lb / 128, NH, NZ), 256, ATTN_SMEM>>>(gq, gk, gv, go);

    gemm_o<<<dim3(Dm / 128, Lb / 128, NZ), 128, GEMM_SMEM_B>>>(
        go, gwt + 3 * WSZ, bo, out);
}

// round 16
// speedup vs baseline: 1.0289x; 1.0289x over previous
#include <cuda_runtime.h>
#include <cstdint>
#include <cmath>

// Problem constants
constexpr int Dm   = 1024;   // d_model
constexpr int Lb   = 1024;   // block length (SEQ / SPLIT)
constexpr int NSP  = 4;      // SPLIT
constexpr int NB   = 4;      // batch
constexpr int NH   = 16;     // heads
constexpr int DK   = 64;     // head dim
constexpr int NZ   = NB * NSP;  // 16 independent (b,s) blocks
constexpr int DW   = Dm / 2;    // 512 packed fp16-pair words per row

// Scratch (allocation-free rule: __device__ globals). All fp16, packed as
// uint32 words = 2 fp16 along the contraction/dk dim, PLAIN layout.
__device__ uint32_t g_Q[(size_t)NZ * Lb * DW];   // scaled by log2e/8 already
__device__ uint32_t g_K[(size_t)NZ * Lb * DW];
__device__ uint32_t g_V[(size_t)NZ * Lb * DW];
__device__ uint32_t g_O[(size_t)NZ * Lb * DW];
__device__ uint32_t g_Xc[(size_t)NZ * Lb * DW];
__device__ uint32_t g_Wt[(size_t)4 * NSP * Dm * DW];  // W^T [n][k-words]

__device__ __forceinline__ uint32_t pack2(float lo, float hi) {
    uint32_t r;
    asm("cvt.rn.f16x2.f32 %0, %1, %2;" : "=r"(r) : "f"(hi), "f"(lo));
    return r;
}

__device__ __forceinline__ uint32_t hex2(uint32_t x) {   // 2x fp16 exp2
    uint32_t r;
    asm("ex2.approx.f16x2 %0, %1;" : "=r"(r) : "r"(x));
    return r;
}

__device__ __forceinline__ uint32_t smem_u32(const void* p) {
    uint32_t a;
    asm("{ .reg .u64 t; cvta.to.shared.u64 t, %1; cvt.u32.u64 %0, t; }"
        : "=r"(a) : "l"(p));
    return a;
}

__device__ __forceinline__ void cp16(uint32_t dst, const void* src) {
    asm volatile("cp.async.cg.shared.global [%0], [%1], 16;"
                 :: "r"(dst), "l"(src) : "memory");
}
#define CP_COMMIT() asm volatile("cp.async.commit_group;" ::: "memory")
#define CP_WAIT1()  asm volatile("cp.async.wait_group 1;" ::: "memory")
#define CP_WAIT2()  asm volatile("cp.async.wait_group 2;" ::: "memory")

#define LDSM4(d0, d1, d2, d3, a)                                            \
    asm volatile("ldmatrix.sync.aligned.m8n8.x4.shared.b16 {%0,%1,%2,%3}, [%4];" \
        : "=r"(d0), "=r"(d1), "=r"(d2), "=r"(d3) : "r"(a))
#define LDSM4T(d0, d1, d2, d3, a)                                           \
    asm volatile("ldmatrix.sync.aligned.m8n8.x4.trans.shared.b16 {%0,%1,%2,%3}, [%4];" \
        : "=r"(d0), "=r"(d1), "=r"(d2), "=r"(d3) : "r"(a))

__device__ __forceinline__ void mma_f16(float c[4], uint32_t a0, uint32_t a1,
                                        uint32_t a2, uint32_t a3,
                                        uint32_t b0, uint32_t b1) {
    asm volatile(
        "mma.sync.aligned.m16n8k16.row.col.f32.f16.f16.f32 "
        "{%0,%1,%2,%3}, {%4,%5,%6,%7}, {%8,%9}, {%0,%1,%2,%3};\n"
        : "+f"(c[0]), "+f"(c[1]), "+f"(c[2]), "+f"(c[3])
        : "r"(a0), "r"(a1), "r"(a2), "r"(a3), "r"(b0), "r"(b1));
}

// ============================================================================
// Converts (one-time prep)
// ============================================================================
__global__ __launch_bounds__(256) void convert_x_pack(const float* __restrict__ src,
                                                      uint32_t* __restrict__ dst) {
    size_t g = (size_t)blockIdx.x * 256 + threadIdx.x;   // 8-float group
    const float4* s = (const float4*)src + g * 2;
    float4 a = s[0], b = s[1];
    uint4 o;
    o.x = pack2(a.x, a.y); o.y = pack2(a.z, a.w);
    o.z = pack2(b.x, b.y); o.w = pack2(b.z, b.w);
    ((uint4*)dst)[g] = o;
}

__global__ __launch_bounds__(256) void convert_w_t(const float* __restrict__ w0,
                                                   const float* __restrict__ w1,
                                                   const float* __restrict__ w2,
                                                   const float* __restrict__ w3,
                                                   uint32_t* __restrict__ dst) {
    __shared__ float t[32][33];
    const int zz = blockIdx.z;           // 0..15
    const int p = zz >> 2, s = zz & 3;
    const float* src = (p == 0) ? w0 : (p == 1) ? w1 : (p == 2) ? w2 : w3;
    const float* Wb = src + (size_t)s * Dm * Dm;
    uint32_t* Tw = dst + ((size_t)p * NSP + s) * Dm * DW;

    const int k0 = blockIdx.y * 32, n0 = blockIdx.x * 32;
    const int x = threadIdx.x & 31, y = threadIdx.x >> 5;   // 32 x 8
#pragma unroll
    for (int i = 0; i < 32; i += 8)
        t[y + i][x] = Wb[(size_t)(k0 + y + i) * Dm + n0 + x];
    __syncthreads();
    const int r = threadIdx.x & 31, w = threadIdx.x >> 5;   // row r, words w,w+8
    Tw[(size_t)(n0 + r) * DW + (k0 >> 1) + w]     = pack2(t[2 * w][r],      t[2 * w + 1][r]);
    Tw[(size_t)(n0 + r) * DW + (k0 >> 1) + w + 8] = pack2(t[2 * w + 16][r], t[2 * w + 17][r]);
}

// ============================================================================
// fp16 GEMM core (unchanged): 128 threads, 4 warps x 64x64, cp.async 3-stage,
// ldmatrix fragments, block(4w)-swizzle b' = b ^ ((r>>1)&3).
// ============================================================================
constexpr int GW      = 16;              // words per tile row (32 k)
constexpr int TILE_AW = 128 * GW;        // 2048 words
constexpr int STG_W   = 2 * TILE_AW;     // 4096 words = 16KB
constexpr int NSTAGE  = 3;
constexpr int GEMM_SMEM_B = NSTAGE * STG_W * 4;   // 49152 B

template <bool F16OUT>
__device__ __forceinline__ void gemm_core(const uint32_t* __restrict__ Xw,
                                          const uint32_t* __restrict__ Ww,
                                          const float* __restrict__ bz,
                                          void* __restrict__ Cz,
                                          uint32_t* smw, float sc) {
    const uint32_t sb = smem_u32(smw);
    const int m0 = blockIdx.y * 128, n0 = blockIdx.x * 128;
    const uint32_t* Xb = Xw + (size_t)m0 * DW;
    const uint32_t* Wb = Ww + (size_t)n0 * DW;
    const float* bb = bz + n0;

    const int tid = threadIdx.x;
    const int wid = tid >> 5, lane = tid & 31;
    const int gid = lane >> 2, t4 = lane & 3;
    const int wm = (wid & 1) * 64, wn = (wid >> 1) * 64;

    const int sr = tid >> 2, sb4 = tid & 3;      // staging: 32 rows/pass x 4 blocks
    auto stage = [&](int c) {
        uint32_t base = sb + (uint32_t)(c % NSTAGE) * (STG_W * 4);
#pragma unroll
        for (int i = 0; i < 4; i++) {
            int r = sr + i * 32;
            int bp = sb4 ^ ((r >> 1) & 3);
            cp16(base + (uint32_t)(r * GW + 4 * bp) * 4,
                 Xb + (size_t)r * DW + c * GW + sb4 * 4);
            cp16(base + (uint32_t)(TILE_AW + r * GW + 4 * bp) * 4,
                 Wb + (size_t)r * DW + c * GW + sb4 * 4);
        }
    };

    float acc[4][8][4];
#pragma unroll
    for (int i = 0; i < 4; i++)
#pragma unroll
        for (int j = 0; j < 8; j++)
#pragma unroll
            for (int k = 0; k < 4; k++) acc[i][j][k] = 0.f;

    stage(0); CP_COMMIT();
    stage(1); CP_COMMIT();

    const int l7 = lane & 7, l3 = (lane >> 3) & 1, l4 = lane >> 4;
    const int NCHUNK = Dm / 32;   // 32
    for (int c = 0; c < NCHUNK; c++) {
        CP_WAIT1();
        __syncthreads();
        if (c + 2 < NCHUNK) stage(c + 2);
        CP_COMMIT();

        const uint32_t sa = sb + (uint32_t)(c % NSTAGE) * (STG_W * 4);
        const uint32_t sbB = sa + TILE_AW * 4;
#pragma unroll
        for (int g = 0; g < 2; g++) {
            uint32_t af[4][4], bf[8][2];
#pragma unroll
            for (int mt = 0; mt < 4; mt++) {
                int ra = wm + mt * 16 + l7 + 8 * l3;
                int b  = 2 * g + l4;
                uint32_t ad = sa + (uint32_t)(ra * GW + 4 * (b ^ ((ra >> 1) & 3))) * 4;
                LDSM4(af[mt][0], af[mt][1], af[mt][2], af[mt][3], ad);
            }
#pragma unroll
            for (int p = 0; p < 4; p++) {
                int rb = wn + 16 * p + 8 * l4 + l7;
                int b  = 2 * g + l3;
                uint32_t ad = sbB + (uint32_t)(rb * GW + 4 * (b ^ ((rb >> 1) & 3))) * 4;
                LDSM4(bf[2 * p][0], bf[2 * p][1], bf[2 * p + 1][0], bf[2 * p + 1][1], ad);
            }
#pragma unroll
            for (int mt = 0; mt < 4; mt++)
#pragma unroll
                for (int nt = 0; nt < 8; nt++)
                    mma_f16(acc[mt][nt], af[mt][0], af[mt][1], af[mt][2], af[mt][3],
                            bf[nt][0], bf[nt][1]);
        }
    }

    // Epilogue: + bias, * sc; F16OUT packs fp16 pairs, else fp32 float2.
#pragma unroll
    for (int mt = 0; mt < 4; mt++) {
        int r0 = wm + mt * 16 + gid;
#pragma unroll
        for (int nt = 0; nt < 8; nt++) {
            int c0 = wn + nt * 8 + 2 * t4;
            float bv0 = bb[c0], bv1 = bb[c0 + 1];
            float v0 = (acc[mt][nt][0] + bv0) * sc, v1 = (acc[mt][nt][1] + bv1) * sc;
            float v2 = (acc[mt][nt][2] + bv0) * sc, v3 = (acc[mt][nt][3] + bv1) * sc;
            if (F16OUT) {
                uint32_t* Cw = (uint32_t*)Cz + (size_t)(m0) * DW + (n0 >> 1);
                int wc = (wn >> 1) + nt * 4 + t4;
                Cw[(size_t)r0 * DW + wc]       = pack2(v0, v1);
                Cw[(size_t)(r0 + 8) * DW + wc] = pack2(v2, v3);
            } else {
                float* Cf = (float*)Cz + (size_t)m0 * Dm + n0;
                *(float2*)(Cf + (size_t)r0 * Dm + c0)       = make_float2(v0, v1);
                *(float2*)(Cf + (size_t)(r0 + 8) * Dm + c0) = make_float2(v2, v3);
            }
        }
    }
}

__global__ __launch_bounds__(128) void gemm_qkv(const uint32_t* __restrict__ X,
                                                const uint32_t* __restrict__ Wt,
                                                const float* __restrict__ bq,
                                                const float* __restrict__ bk,
                                                const float* __restrict__ bv,
                                                uint32_t* __restrict__ Qo,
                                                uint32_t* __restrict__ Ko,
                                                uint32_t* __restrict__ Vo) {
    extern __shared__ uint32_t smw[];
    const int proj = blockIdx.z / NZ;
    const int z    = blockIdx.z % NZ;
    const size_t WSZ = (size_t)NSP * Dm * DW;
    const uint32_t* Xz = X + (size_t)z * Lb * DW;
    const uint32_t* Wz = Wt + proj * WSZ + (size_t)(z % NSP) * Dm * DW;
    const float* bz = ((proj == 0) ? bq : (proj == 1) ? bk : bv)
                      + (size_t)(z % NSP) * Dm;
    uint32_t* Cz = ((proj == 0) ? Qo : (proj == 1) ? Ko : Vo) + (size_t)z * Lb * DW;
    // fold 1/sqrt(DK) AND log2(e) into Q so softmax uses raw exp2
    float sc = (proj == 0) ? 0.125f * 1.44269504088896340736f : 1.0f;
    gemm_core<true>(Xz, Wz, bz, Cz, smw, sc);
}

__global__ __launch_bounds__(128) void gemm_o(const uint32_t* __restrict__ X,
                                              const uint32_t* __restrict__ Wtz4,
                                              const float* __restrict__ bo,
                                              float* __restrict__ out) {
    extern __shared__ uint32_t smw[];
    const int z = blockIdx.z;
    gemm_core<false>(X + (size_t)z * Lb * DW,
                     Wtz4 + (size_t)(z % NSP) * Dm * DW,
                     bo + (size_t)(z % NSP) * Dm,
                     out + (size_t)z * Lb * Dm, smw, 1.0f);
}

// ============================================================================
// fp16 flash attention v3: 256 threads, 128-row q-tiles, 4-stage cp.async,
// single barrier per key tile. NEW: P computed with ex2.approx.f16x2 (halves
// the MUFU stream — the measured bottleneck) and row-sums via a ones-MMA
// (kills the FADD+SHFL reduction chain; numerator/denominator use identical
// fp16 P values).
// ============================================================================
constexpr int KVW = 64 * 32;                       // words per K (or V) tile
constexpr int KV_STG_W = 2 * KVW;                  // K+V per stage = 4096 words
constexpr int KV_NSTG  = 4;
constexpr int Q_OFF_W  = KV_NSTG * KV_STG_W;       // 16384
constexpr int ATTN_SMEM = (Q_OFF_W + 128 * 32) * 4;  // 81920 B -> 2 CTAs/SM
constexpr uint32_t ONES2 = 0x3C003C00u;            // (1.0h, 1.0h)

__global__ __launch_bounds__(256, 2) void attn_kernel(const uint32_t* __restrict__ Q,
                                                      const uint32_t* __restrict__ K,
                                                      const uint32_t* __restrict__ V,
                                                      uint32_t* __restrict__ O) {
    extern __shared__ uint32_t sm[];
    const uint32_t sb = smem_u32(sm);
    const uint32_t qb = sb + Q_OFF_W * 4;

    const int qt = blockIdx.x;
    const int h  = blockIdx.y;
    const int z  = blockIdx.z;
    const size_t base = (size_t)z * Lb * DW + h * (DK / 2);   // word base

    const int tid = threadIdx.x;
    const int wid = tid >> 5, lane = tid & 31;
    const int gid = lane >> 2, t4 = lane & 3;
    const int wrow = wid * 16;
    const int l7 = lane & 7, l3 = (lane >> 3) & 1, l4 = lane >> 4;
    const int jlast = 2 * qt + (wid >= 4 ? 1 : 0);
    const int jend  = 2 * qt + 1;

    // Stage Q tile (already scaled by log2e/8 in projection) — with group 0
    {
        const int r8 = tid >> 3, b = tid & 7;
#pragma unroll
        for (int i = 0; i < 4; i++) {
            int r = r8 + i * 32;
            cp16(qb + (uint32_t)(r * 32 + 4 * (b ^ (r & 7))) * 4,
                 Q + base + (size_t)(qt * 128 + r) * DW + 4 * b);
        }
    }
    auto stageKV = [&](int j) {
        uint32_t kbase = sb + (uint32_t)((j & 3) * KV_STG_W) * 4;
        uint32_t vbase = kbase + (uint32_t)KVW * 4;
        const int r8 = tid >> 3, b = tid & 7;
#pragma unroll
        for (int i = 0; i < 2; i++) {
            int r = r8 + i * 32;
            uint32_t off = (uint32_t)(r * 32 + 4 * (b ^ (r & 7))) * 4;
            size_t src = base + (size_t)(j * 64 + r) * DW + 4 * b;
            cp16(kbase + off, K + src);
            cp16(vbase + off, V + src);
        }
    };

    stageKV(0); CP_COMMIT();     // group 0 also contains Q
    stageKV(1); CP_COMMIT();

    uint32_t qa[4][4];
    float acc[8][4];
#pragma unroll
    for (int nt = 0; nt < 8; nt++)
#pragma unroll
        for (int k = 0; k < 4; k++) acc[nt][k] = 0.f;
    float mrow0 = -INFINITY, mrow1 = -INFINITY;
    float lrow0 = 0.f, lrow1 = 0.f;

    for (int j = 0; j <= jend; j++) {
        if (j + 2 <= jend) stageKV(j + 2);
        CP_COMMIT();
        CP_WAIT2();          // group j complete (<=2 outstanding: j+1, j+2)
        __syncthreads();     // publish group j across warps

        if (j == 0) {   // Q landed with group 0 — load A-fragments once
#pragma unroll
            for (int g = 0; g < 4; g++) {
                int r = wrow + l7 + 8 * l3;
                int b = 2 * g + l4;
                uint32_t ad = qb + (uint32_t)(r * 32 + 4 * (b ^ (r & 7))) * 4;
                LDSM4(qa[g][0], qa[g][1], qa[g][2], qa[g][3], ad);
            }
        }

        const uint32_t kst = sb + (uint32_t)((j & 3) * KV_STG_W) * 4;
        const uint32_t vst = kst + (uint32_t)KVW * 4;

        if (j <= jlast) {
            // ---- S = Q K^T (scores pre-scaled by log2e) ----
            float s[8][4];
#pragma unroll
            for (int nt = 0; nt < 8; nt++)
#pragma unroll
                for (int k = 0; k < 4; k++) s[nt][k] = 0.f;
#pragma unroll
            for (int g = 0; g < 4; g++) {
                uint32_t kb[8][2];
#pragma unroll
                for (int p = 0; p < 4; p++) {
                    int rb = 16 * p + 8 * l4 + l7;
                    int b  = 2 * g + l3;
                    uint32_t ad = kst + (uint32_t)(rb * 32 + 4 * (b ^ (rb & 7))) * 4;
                    LDSM4(kb[2 * p][0], kb[2 * p][1], kb[2 * p + 1][0], kb[2 * p + 1][1], ad);
                }
#pragma unroll
                for (int nt = 0; nt < 8; nt++)
                    mma_f16(s[nt], qa[g][0], qa[g][1], qa[g][2], qa[g][3],
                            kb[nt][0], kb[nt][1]);
            }

            // ---- causal mask on the warp's final tile ----
            if (j == jlast) {
                int koff = (j - 2 * qt) * 64;
                int r0 = wrow + gid, r1 = wrow + gid + 8;
#pragma unroll
                for (int nt = 0; nt < 8; nt++) {
                    int c0 = koff + nt * 8 + 2 * t4;
                    if (c0 > r0)     s[nt][0] = -1e30f;
                    if (c0 + 1 > r0) s[nt][1] = -1e30f;
                    if (c0 > r1)     s[nt][2] = -1e30f;
                    if (c0 + 1 > r1) s[nt][3] = -1e30f;
                }
            }

            // ---- online softmax: row max (fp32) ----
            float mx0 = -INFINITY, mx1 = -INFINITY;
#pragma unroll
            for (int nt = 0; nt < 8; nt++) {
                mx0 = fmaxf(mx0, fmaxf(s[nt][0], s[nt][1]));
                mx1 = fmaxf(mx1, fmaxf(s[nt][2], s[nt][3]));
            }
            mx0 = fmaxf(mx0, __shfl_xor_sync(0xffffffffu, mx0, 1));
            mx0 = fmaxf(mx0, __shfl_xor_sync(0xffffffffu, mx0, 2));
            mx1 = fmaxf(mx1, __shfl_xor_sync(0xffffffffu, mx1, 1));
            mx1 = fmaxf(mx1, __shfl_xor_sync(0xffffffffu, mx1, 2));

            float mn0 = fmaxf(mrow0, mx0), mn1 = fmaxf(mrow1, mx1);
            float cor0 = exp2f(mrow0 - mn0), cor1 = exp2f(mrow1 - mn1);
            mrow0 = mn0; mrow1 = mn1;

#pragma unroll
            for (int nt = 0; nt < 8; nt++) {
                acc[nt][0] *= cor0; acc[nt][1] *= cor0;
                acc[nt][2] *= cor1; acc[nt][3] *= cor1;
            }

            // ---- P = ex2.f16x2(s - mn); O += P V; row-sum via ones-MMA ----
            float lsum[4] = {0.f, 0.f, 0.f, 0.f};
#pragma unroll
            for (int g = 0; g < 4; g++) {
                uint32_t pa0 = hex2(pack2(s[2 * g][0] - mn0,     s[2 * g][1] - mn0));
                uint32_t pa1 = hex2(pack2(s[2 * g][2] - mn1,     s[2 * g][3] - mn1));
                uint32_t pa2 = hex2(pack2(s[2 * g + 1][0] - mn0, s[2 * g + 1][1] - mn0));
                uint32_t pa3 = hex2(pack2(s[2 * g + 1][2] - mn1, s[2 * g + 1][3] - mn1));
                mma_f16(lsum, pa0, pa1, pa2, pa3, ONES2, ONES2);
                uint32_t vb[8][2];
#pragma unroll
                for (int p = 0; p < 4; p++) {
                    int rv = 16 * g + l7 + 8 * l3;
                    int b  = 2 * p + l4;
                    uint32_t ad = vst + (uint32_t)(rv * 32 + 4 * (b ^ (rv & 7))) * 4;
                    LDSM4T(vb[2 * p][0], vb[2 * p][1], vb[2 * p + 1][0], vb[2 * p + 1][1], ad);
                }
#pragma unroll
                for (int nt = 0; nt < 8; nt++)
                    mma_f16(acc[nt], pa0, pa1, pa2, pa3, vb[nt][0], vb[nt][1]);
            }
            // lsum[0] = rowsum(row gid), lsum[2] = rowsum(row gid+8) (cols equal)
            lrow0 = lrow0 * cor0 + lsum[0];
            lrow1 = lrow1 * cor1 + lsum[2];
        }
    }

    // Finalize: /rowsum, pack fp16, plain layout
    float inv0 = 1.f / lrow0, inv1 = 1.f / lrow1;
    int r0 = qt * 128 + wrow + gid;
#pragma unroll
    for (int nt = 0; nt < 8; nt++) {
        int wc = nt * 4 + t4;
        O[base + (size_t)r0 * DW + wc]       = pack2(acc[nt][0] * inv0, acc[nt][1] * inv0);
        O[base + (size_t)(r0 + 8) * DW + wc] = pack2(acc[nt][2] * inv1, acc[nt][3] * inv1);
    }
}

// ============================================================================
// Launch
// ============================================================================
extern "C" void kernel_launch(void* const* d_in, const int* in_sizes, int n_in,
                              void* d_out, int out_size) {
    const float* x  = (const float*)d_in[0];
    const float* Wq = (const float*)d_in[1];
    const float* Wk = (const float*)d_in[2];
    const float* Wv = (const float*)d_in[3];
    const float* Wo = (const float*)d_in[4];
    const float* bq = (const float*)d_in[5];
    const float* bk = (const float*)d_in[6];
    const float* bv = (const float*)d_in[7];
    const float* bo = (const float*)d_in[8];
    float* out = (float*)d_out;

    uint32_t *gq, *gk, *gv, *go, *gxc, *gwt;
    cudaGetSymbolAddress((void**)&gq, g_Q);
    cudaGetSymbolAddress((void**)&gk, g_K);
    cudaGetSymbolAddress((void**)&gv, g_V);
    cudaGetSymbolAddress((void**)&go, g_O);
    cudaGetSymbolAddress((void**)&gxc, g_Xc);
    cudaGetSymbolAddress((void**)&gwt, g_Wt);
    const size_t WSZ = (size_t)NSP * Dm * DW;

    cudaFuncSetAttribute(attn_kernel, cudaFuncAttributeMaxDynamicSharedMemorySize,
                         ATTN_SMEM);
    cudaFuncSetAttribute(gemm_qkv, cudaFuncAttributeMaxDynamicSharedMemorySize,
                         GEMM_SMEM_B);
    cudaFuncSetAttribute(gemm_o, cudaFuncAttributeMaxDynamicSharedMemorySize,
                         GEMM_SMEM_B);

    const size_t XG = (size_t)NZ * Lb * Dm / 8;     // 8-float groups
    convert_x_pack<<<(unsigned)(XG / 256), 256>>>(x, gxc);
    convert_w_t<<<dim3(32, 32, 16), 256>>>(Wq, Wk, Wv, Wo, gwt);

    gemm_qkv<<<dim3(Dm / 128, Lb / 128, NZ * 3), 128, GEMM_SMEM_B>>>(
        gxc, gwt, bq, bk, bv, gq, gk, gv);

    attn_kernel<<<dim3(Lb / 128, NH, NZ), 256, ATTN_SMEM>>>(gq, gk, gv, go);

    gemm_o<<<dim3(Dm / 128, Lb / 128, NZ), 128, GEMM_SMEM_B>>>(
        go, gwt + 3 * WSZ, bo, out);
}